// round 2
// baseline (speedup 1.0000x reference)
#include <cuda_runtime.h>
#include <cuda_bf16.h>
#include <cstdint>

// ---------------------------------------------------------------------------
// CrossAttentionLayer: B=16, S=512, D=1024, H=16, hd=64, window +-64
// out = LN(0.5*h + 0.5*sigmoid(h@Wg^T+bg) * ((softmax_banded(QK^T*s)V)@Wo^T+bo))
// ---------------------------------------------------------------------------

#define BATCH 16
#define SEQ   512
#define DIM   1024
#define HEADS 16
#define HDIM  64
#define ROWS  (BATCH*SEQ)          // 8192
#define NELEM (ROWS*DIM)           // 8388608

// ---------------- scratch (static device allocations are allowed) ----------
static __device__ __align__(16) __nv_bfloat16 g_hb[NELEM];
static __device__ __align__(16) __nv_bfloat16 g_cb[NELEM];
static __device__ __align__(16) __nv_bfloat16 g_w5[5*DIM*DIM];   // Wq,Wk,Wv,Wo,Wg
static __device__ __align__(16) __nv_bfloat16 g_qs[NELEM];
static __device__ __align__(16) __nv_bfloat16 g_ks[NELEM];
static __device__ __align__(16) __nv_bfloat16 g_vs[NELEM];
static __device__ __align__(16) __nv_bfloat16 g_gs[NELEM];
static __device__ __align__(16) __nv_bfloat16 g_at[NELEM];
static __device__ __align__(16) float         g_z [NELEM];

// ---------------- small PTX helpers ----------------------------------------
__device__ __forceinline__ uint32_t smem_u32(const void* p) {
    return (uint32_t)__cvta_generic_to_shared(p);
}
__device__ __forceinline__ void cp_async16(uint32_t dst, const void* src) {
    asm volatile("cp.async.cg.shared.global [%0], [%1], 16;\n" :: "r"(dst), "l"(src));
}
__device__ __forceinline__ void cp_commit() { asm volatile("cp.async.commit_group;\n"); }
__device__ __forceinline__ void cp_wait0()  { asm volatile("cp.async.wait_group 0;\n"); }

__device__ __forceinline__ void ldm_x4(uint32_t& r0, uint32_t& r1, uint32_t& r2, uint32_t& r3,
                                       uint32_t addr) {
    asm volatile("ldmatrix.sync.aligned.m8n8.x4.shared.b16 {%0,%1,%2,%3},[%4];\n"
                 : "=r"(r0), "=r"(r1), "=r"(r2), "=r"(r3) : "r"(addr));
}
__device__ __forceinline__ void mma16816(float* c, const uint32_t* a, const uint32_t* b) {
    asm volatile(
        "mma.sync.aligned.m16n8k16.row.col.f32.bf16.bf16.f32 "
        "{%0,%1,%2,%3},{%4,%5,%6,%7},{%8,%9},{%0,%1,%2,%3};\n"
        : "+f"(c[0]), "+f"(c[1]), "+f"(c[2]), "+f"(c[3])
        : "r"(a[0]), "r"(a[1]), "r"(a[2]), "r"(a[3]), "r"(b[0]), "r"(b[1]));
}
__device__ __forceinline__ uint32_t packbf(float a, float b) {
    __nv_bfloat162 h = __floats2bfloat162_rn(a, b);
    return *reinterpret_cast<const uint32_t*>(&h);
}

// ---------------- fp32 -> bf16 converts -------------------------------------
// activations: hidden -> g_hb, cross -> g_cb in one grid-strided launch
__global__ __launch_bounds__(256, 4) void cvt_act_kernel(
    const float4* __restrict__ h, const float4* __restrict__ c)
{
    const int n4 = NELEM / 4;
    __nv_bfloat162* yh = (__nv_bfloat162*)g_hb;
    __nv_bfloat162* yc = (__nv_bfloat162*)g_cb;
    for (int i = blockIdx.x * blockDim.x + threadIdx.x; i < n4;
         i += gridDim.x * blockDim.x) {
        float4 v = h[i];
        yh[2*i]   = __floats2bfloat162_rn(v.x, v.y);
        yh[2*i+1] = __floats2bfloat162_rn(v.z, v.w);
        float4 u = c[i];
        yc[2*i]   = __floats2bfloat162_rn(u.x, u.y);
        yc[2*i+1] = __floats2bfloat162_rn(u.z, u.w);
    }
}
// weights: 5 x [DIM*DIM], picked by blockIdx.y
__global__ __launch_bounds__(256, 4) void cvt_w_kernel(
    const float4* __restrict__ w0, const float4* __restrict__ w1,
    const float4* __restrict__ w2, const float4* __restrict__ w3,
    const float4* __restrict__ w4)
{
    const float4* src[5] = {w0, w1, w2, w3, w4};
    const int n4 = (DIM * DIM) / 4;
    const float4* x = src[blockIdx.y];
    __nv_bfloat162* y = (__nv_bfloat162*)(g_w5 + (size_t)blockIdx.y * DIM * DIM);
    for (int i = blockIdx.x * blockDim.x + threadIdx.x; i < n4;
         i += gridDim.x * blockDim.x) {
        float4 v = x[i];
        y[2*i]   = __floats2bfloat162_rn(v.x, v.y);
        y[2*i+1] = __floats2bfloat162_rn(v.z, v.w);
    }
}

// ---------------- GEMM: C[M,N] = A[M,K] * W[N,K]^T (+bias, epilogue) --------
// 128x128x32 tiles, 256 threads = 8 warps (4m x 2n), warp tile 32x64.
// MODE 0: outb = bf16(acc + bias)
// MODE 1: outf = 0.5*h + 0.5*sigmoid(g)*(acc + bias)
template <int MODE>
__global__ __launch_bounds__(256, 1) void gemm_kernel(
    const __nv_bfloat16* __restrict__ A, const __nv_bfloat16* __restrict__ W,
    const float* __restrict__ bias, __nv_bfloat16* __restrict__ outb,
    const float* __restrict__ hres, const __nv_bfloat16* __restrict__ gate,
    float* __restrict__ outf, int M, int N, int K)
{
    __shared__ __align__(16) __nv_bfloat16 sA[2][128*40];
    __shared__ __align__(16) __nv_bfloat16 sB[2][128*40];

    const int tid  = threadIdx.x;
    const int lane = tid & 31;
    const int warp = tid >> 5;
    const int wm   = warp & 3;
    const int wn   = warp >> 2;
    const int m0   = blockIdx.y * 128;
    const int n0   = blockIdx.x * 128;

    float acc[2][8][4];
#pragma unroll
    for (int i = 0; i < 2; i++)
#pragma unroll
        for (int j = 0; j < 8; j++)
#pragma unroll
            for (int e = 0; e < 4; e++) acc[i][j][e] = 0.f;

    auto load_stage = [&](int kt, int buf) {
        int k0 = kt * 32;
#pragma unroll
        for (int c = 0; c < 2; c++) {
            int ch = c * 256 + tid;          // 0..511
            int r  = ch >> 2;                // 0..127
            int ko = (ch & 3) * 8;           // 0,8,16,24
            cp_async16(smem_u32(&sA[buf][r*40 + ko]), A + (size_t)(m0 + r) * K + k0 + ko);
            cp_async16(smem_u32(&sB[buf][r*40 + ko]), W + (size_t)(n0 + r) * K + k0 + ko);
        }
        cp_commit();
    };

    const int nkt = K >> 5;
    load_stage(0, 0);
    for (int kt = 0; kt < nkt; kt++) {
        cp_wait0();
        __syncthreads();
        if (kt + 1 < nkt) load_stage(kt + 1, (kt + 1) & 1);
        const __nv_bfloat16* cA = sA[kt & 1];
        const __nv_bfloat16* cB = sB[kt & 1];
#pragma unroll
        for (int ks = 0; ks < 2; ks++) {
            int kk = ks * 16;
            uint32_t a[2][4];
#pragma unroll
            for (int i = 0; i < 2; i++) {
                int row = wm*32 + i*16 + (lane & 15);
                int col = kk + ((lane >> 4) << 3);
                ldm_x4(a[i][0], a[i][1], a[i][2], a[i][3], smem_u32(cA + row*40 + col));
            }
#pragma unroll
            for (int jp = 0; jp < 4; jp++) {
                uint32_t b[4];
                int nrow = wn*64 + jp*16 + (lane & 7) + ((lane >> 4) << 3);
                int col  = kk + (lane & 8);
                ldm_x4(b[0], b[1], b[2], b[3], smem_u32(cB + nrow*40 + col));
#pragma unroll
                for (int i = 0; i < 2; i++) {
                    mma16816(acc[i][2*jp],   a[i], b);
                    mma16816(acc[i][2*jp+1], a[i], b + 2);
                }
            }
        }
        __syncthreads();
    }

    // epilogue
#pragma unroll
    for (int i = 0; i < 2; i++) {
        int r0 = m0 + wm*32 + i*16 + (lane >> 2);
#pragma unroll
        for (int j = 0; j < 8; j++) {
            int c = n0 + wn*64 + j*8 + 2*(lane & 3);
            float b0 = bias[c], b1 = bias[c+1];
            float v00 = acc[i][j][0] + b0, v01 = acc[i][j][1] + b1;
            float v10 = acc[i][j][2] + b0, v11 = acc[i][j][3] + b1;
            size_t i0 = (size_t)r0 * N + c;
            size_t i1 = (size_t)(r0 + 8) * N + c;
            if (MODE == 0) {
                *(uint32_t*)(outb + i0) = packbf(v00, v01);
                *(uint32_t*)(outb + i1) = packbf(v10, v11);
            } else {
                float ga, gb;
                ga = __bfloat162float(gate[i0]);     gb = __bfloat162float(gate[i0+1]);
                outf[i0]   = 0.5f*hres[i0]   + 0.5f * (1.f/(1.f+__expf(-ga))) * v00;
                outf[i0+1] = 0.5f*hres[i0+1] + 0.5f * (1.f/(1.f+__expf(-gb))) * v01;
                ga = __bfloat162float(gate[i1]);     gb = __bfloat162float(gate[i1+1]);
                outf[i1]   = 0.5f*hres[i1]   + 0.5f * (1.f/(1.f+__expf(-ga))) * v10;
                outf[i1+1] = 0.5f*hres[i1+1] + 0.5f * (1.f/(1.f+__expf(-gb))) * v11;
            }
        }
    }
}

// ---------------- banded attention ------------------------------------------
// CTA = (qtile t, head h, batch b); 64 queries, up to 192 keys [q0-64, q0+127].
// 4 warps; warp w owns q rows [w*16, w*16+16).
__global__ __launch_bounds__(128, 1) void attn_kernel(
    const __nv_bfloat16* __restrict__ Q, const __nv_bfloat16* __restrict__ Kp,
    const __nv_bfloat16* __restrict__ V, __nv_bfloat16* __restrict__ O)
{
    __shared__ __align__(16) __nv_bfloat16 sm[18432];   // 36 KB
    __nv_bfloat16* Qs = sm;            // [64][72]
    __nv_bfloat16* Ks = sm + 64*72;    // [192][72]

    const int t = blockIdx.x, h = blockIdx.y, b = blockIdx.z;
    const int tid = threadIdx.x, lane = tid & 31, w = tid >> 5;
    const int q0 = t * 64;
    int lo = q0 - 64; if (lo < 0) lo = 0;
    int hi = q0 + 127; if (hi > SEQ - 1) hi = SEQ - 1;
    const int nk = hi - lo + 1;
    const size_t base = ((size_t)b * SEQ) * DIM + h * HDIM;

    // load Q tile (64x64)
    for (int c = tid; c < 512; c += 128) {
        int r = c >> 3, off = (c & 7) << 3;
        *(uint4*)(Qs + r*72 + off) =
            *(const uint4*)(Q + base + (size_t)(q0 + r) * DIM + off);
    }
    // load K tile (192x64, zero-padded)
    for (int c = tid; c < 1536; c += 128) {
        int jj = c >> 3, off = (c & 7) << 3;
        uint4 d = make_uint4(0u, 0u, 0u, 0u);
        if (jj < nk) d = *(const uint4*)(Kp + base + (size_t)(lo + jj) * DIM + off);
        *(uint4*)(Ks + jj*72 + off) = d;
    }
    __syncthreads();

    // S = Q K^T  (16 x 192 per warp)
    float s[24][4];
#pragma unroll
    for (int j = 0; j < 24; j++)
#pragma unroll
        for (int e = 0; e < 4; e++) s[j][e] = 0.f;

#pragma unroll
    for (int ks = 0; ks < 4; ks++) {
        int kk = ks * 16;
        uint32_t a[4];
        {
            int row = w*16 + (lane & 15);
            int col = kk + ((lane >> 4) << 3);
            ldm_x4(a[0], a[1], a[2], a[3], smem_u32(Qs + row*72 + col));
        }
#pragma unroll
        for (int jp = 0; jp < 12; jp++) {
            uint32_t bb[4];
            int nrow = jp*16 + (lane & 7) + ((lane >> 4) << 3);
            int col  = kk + (lane & 8);
            ldm_x4(bb[0], bb[1], bb[2], bb[3], smem_u32(Ks + nrow*72 + col));
            mma16816(s[2*jp],   a, bb);
            mma16816(s[2*jp+1], a, bb + 2);
        }
    }

    // mask + scale + softmax (register-resident)
    const int r0 = q0 + w*16 + (lane >> 2);
    const int r1 = r0 + 8;
    float m0 = -1e30f, m1 = -1e30f;
#pragma unroll
    for (int j = 0; j < 24; j++) {
        int kg = lo + j*8 + 2*(lane & 3);
        int d00 = r0 - kg, d01 = r0 - kg - 1, d10 = r1 - kg, d11 = r1 - kg - 1;
        bool v0 = (kg     <= hi) && (d00 <= 64) && (d00 >= -64);
        bool v1 = (kg + 1 <= hi) && (d01 <= 64) && (d01 >= -64);
        bool v2 = (kg     <= hi) && (d10 <= 64) && (d10 >= -64);
        bool v3 = (kg + 1 <= hi) && (d11 <= 64) && (d11 >= -64);
        s[j][0] = v0 ? s[j][0] * 0.125f : -1e30f;
        s[j][1] = v1 ? s[j][1] * 0.125f : -1e30f;
        s[j][2] = v2 ? s[j][2] * 0.125f : -1e30f;
        s[j][3] = v3 ? s[j][3] * 0.125f : -1e30f;
        m0 = fmaxf(m0, fmaxf(s[j][0], s[j][1]));
        m1 = fmaxf(m1, fmaxf(s[j][2], s[j][3]));
    }
    m0 = fmaxf(m0, __shfl_xor_sync(0xffffffffu, m0, 1));
    m0 = fmaxf(m0, __shfl_xor_sync(0xffffffffu, m0, 2));
    m1 = fmaxf(m1, __shfl_xor_sync(0xffffffffu, m1, 1));
    m1 = fmaxf(m1, __shfl_xor_sync(0xffffffffu, m1, 2));

    float sum0 = 0.f, sum1 = 0.f;
#pragma unroll
    for (int j = 0; j < 24; j++) {
        s[j][0] = __expf(s[j][0] - m0); sum0 += s[j][0];
        s[j][1] = __expf(s[j][1] - m0); sum0 += s[j][1];
        s[j][2] = __expf(s[j][2] - m1); sum1 += s[j][2];
        s[j][3] = __expf(s[j][3] - m1); sum1 += s[j][3];
    }
    sum0 += __shfl_xor_sync(0xffffffffu, sum0, 1);
    sum0 += __shfl_xor_sync(0xffffffffu, sum0, 2);
    sum1 += __shfl_xor_sync(0xffffffffu, sum1, 1);
    sum1 += __shfl_xor_sync(0xffffffffu, sum1, 2);

    __syncthreads();   // all warps done with Qs/Ks

    // load V transposed: Vt[d][k] (64 x 192, stride 200), reusing smem
    __nv_bfloat16* Vt = sm;
    for (int c = tid; c < 1536; c += 128) {
        int jj = c >> 3, off = (c & 7) << 3;
        __nv_bfloat16 tmp[8];
        uint4 d = make_uint4(0u, 0u, 0u, 0u);
        if (jj < nk) d = *(const uint4*)(V + base + (size_t)(lo + jj) * DIM + off);
        *(uint4*)tmp = d;
#pragma unroll
        for (int u = 0; u < 8; u++) Vt[(off + u)*200 + jj] = tmp[u];
    }
    __syncthreads();

    // O = P V   (16 x 64 per warp)
    float o_[8][4];
#pragma unroll
    for (int j = 0; j < 8; j++)
#pragma unroll
        for (int e = 0; e < 4; e++) o_[j][e] = 0.f;

#pragma unroll
    for (int kk = 0; kk < 12; kk++) {
        uint32_t pa[4];
        pa[0] = packbf(s[2*kk][0],   s[2*kk][1]);
        pa[1] = packbf(s[2*kk][2],   s[2*kk][3]);
        pa[2] = packbf(s[2*kk+1][0], s[2*kk+1][1]);
        pa[3] = packbf(s[2*kk+1][2], s[2*kk+1][3]);
#pragma unroll
        for (int dp = 0; dp < 4; dp++) {
            uint32_t bb[4];
            int nrow = dp*16 + (lane & 7) + ((lane >> 4) << 3);
            int col  = kk*16 + (lane & 8);
            ldm_x4(bb[0], bb[1], bb[2], bb[3], smem_u32(Vt + nrow*200 + col));
            mma16816(o_[2*dp],   pa, bb);
            mma16816(o_[2*dp+1], pa, bb + 2);
        }
    }

    const float inv0 = 1.f / sum0, inv1 = 1.f / sum1;
#pragma unroll
    for (int dj = 0; dj < 8; dj++) {
        int cc = dj*8 + 2*(lane & 3);
        *(uint32_t*)(O + base + (size_t)r0 * DIM + cc) = packbf(o_[dj][0]*inv0, o_[dj][1]*inv0);
        *(uint32_t*)(O + base + (size_t)r1 * DIM + cc) = packbf(o_[dj][2]*inv1, o_[dj][3]*inv1);
    }
}

// ---------------- LayerNorm --------------------------------------------------
__global__ __launch_bounds__(256, 1) void ln_kernel(
    const float* __restrict__ z, const float* __restrict__ gamma,
    const float* __restrict__ beta, float* __restrict__ out)
{
    __shared__ float rs[8], rq[8];
    __shared__ float s_mean, s_rstd;
    const int row = blockIdx.x, tid = threadIdx.x;
    const float4 x = ((const float4*)(z + (size_t)row * DIM))[tid];
    float s = x.x + x.y + x.z + x.w;
    float q = x.x*x.x + x.y*x.y + x.z*x.z + x.w*x.w;
#pragma unroll
    for (int o = 16; o > 0; o >>= 1) {
        s += __shfl_xor_sync(0xffffffffu, s, o);
        q += __shfl_xor_sync(0xffffffffu, q, o);
    }
    if ((tid & 31) == 0) { rs[tid >> 5] = s; rq[tid >> 5] = q; }
    __syncthreads();
    if (tid == 0) {
        float S = 0.f, Q2 = 0.f;
#pragma unroll
        for (int i = 0; i < 8; i++) { S += rs[i]; Q2 += rq[i]; }
        float mean = S * (1.f / DIM);
        float var  = Q2 * (1.f / DIM) - mean * mean;
        s_mean = mean;
        s_rstd = rsqrtf(var + 1e-5f);
    }
    __syncthreads();
    const float mean = s_mean, rstd = s_rstd;
    const float4 gm = ((const float4*)gamma)[tid];
    const float4 bt = ((const float4*)beta)[tid];
    float4 y;
    y.x = (x.x - mean) * rstd * gm.x + bt.x;
    y.y = (x.y - mean) * rstd * gm.y + bt.y;
    y.z = (x.z - mean) * rstd * gm.z + bt.z;
    y.w = (x.w - mean) * rstd * gm.w + bt.w;
    ((float4*)(out + (size_t)row * DIM))[tid] = y;
}

// ---------------- launch -----------------------------------------------------
extern "C" void kernel_launch(void* const* d_in, const int* in_sizes, int n_in,
                              void* d_out, int out_size)
{
    const float* hidden = (const float*)d_in[0];
    const float* cross  = (const float*)d_in[1];
    const float* Wq = (const float*)d_in[2];  const float* bq = (const float*)d_in[3];
    const float* Wk = (const float*)d_in[4];  const float* bk = (const float*)d_in[5];
    const float* Wv = (const float*)d_in[6];  const float* bv = (const float*)d_in[7];
    const float* Wo = (const float*)d_in[8];  const float* bo = (const float*)d_in[9];
    const float* Wg = (const float*)d_in[10]; const float* bg = (const float*)d_in[11];
    const float* gamma = (const float*)d_in[12];
    const float* beta  = (const float*)d_in[13];
    float* out = (float*)d_out;

    void *hb, *cb, *w5, *qs, *ks, *vs, *gs, *at, *zz;
    cudaGetSymbolAddress(&hb, g_hb); cudaGetSymbolAddress(&cb, g_cb);
    cudaGetSymbolAddress(&w5, g_w5);
    cudaGetSymbolAddress(&qs, g_qs); cudaGetSymbolAddress(&ks, g_ks);
    cudaGetSymbolAddress(&vs, g_vs); cudaGetSymbolAddress(&gs, g_gs);
    cudaGetSymbolAddress(&at, g_at); cudaGetSymbolAddress(&zz, g_z);

    const __nv_bfloat16* wq = (const __nv_bfloat16*)w5;
    const __nv_bfloat16* wk = wq + (size_t)DIM * DIM;
    const __nv_bfloat16* wv = wk + (size_t)DIM * DIM;
    const __nv_bfloat16* wo = wv + (size_t)DIM * DIM;
    const __nv_bfloat16* wg = wo + (size_t)DIM * DIM;

    cvt_act_kernel<<<2048, 256>>>((const float4*)hidden, (const float4*)cross);
    cvt_w_kernel<<<dim3(128, 5), 256>>>((const float4*)Wq, (const float4*)Wk,
                                        (const float4*)Wv, (const float4*)Wo,
                                        (const float4*)Wg);

    dim3 gg(DIM / 128, ROWS / 128);   // (8, 64)
    gemm_kernel<0><<<gg, 256>>>((const __nv_bfloat16*)hb, wq, bq,
                                (__nv_bfloat16*)qs, nullptr, nullptr, nullptr, ROWS, DIM, DIM);
    gemm_kernel<0><<<gg, 256>>>((const __nv_bfloat16*)cb, wk, bk,
                                (__nv_bfloat16*)ks, nullptr, nullptr, nullptr, ROWS, DIM, DIM);
    gemm_kernel<0><<<gg, 256>>>((const __nv_bfloat16*)cb, wv, bv,
                                (__nv_bfloat16*)vs, nullptr, nullptr, nullptr, ROWS, DIM, DIM);
    gemm_kernel<0><<<gg, 256>>>((const __nv_bfloat16*)hb, wg, bg,
                                (__nv_bfloat16*)gs, nullptr, nullptr, nullptr, ROWS, DIM, DIM);

    attn_kernel<<<dim3(SEQ / 64, HEADS, BATCH), 128>>>(
        (const __nv_bfloat16*)qs, (const __nv_bfloat16*)ks,
        (const __nv_bfloat16*)vs, (__nv_bfloat16*)at);

    gemm_kernel<1><<<gg, 256>>>((const __nv_bfloat16*)at, wo, bo,
                                nullptr, hidden, (const __nv_bfloat16*)gs,
                                (float*)zz, ROWS, DIM, DIM);

    ln_kernel<<<ROWS, 256>>>((const float*)zz, gamma, beta, out);
    (void)in_sizes; (void)n_in; (void)out_size;
}

// round 4
// speedup vs baseline: 1.7633x; 1.7633x over previous
#include <cuda_runtime.h>
#include <cuda_bf16.h>
#include <cstdint>

// ---------------------------------------------------------------------------
// CrossAttentionLayer: B=16, S=512, D=1024, H=16, hd=64, window +-64
// out = LN(0.5*h + 0.5*sigmoid(h@Wg^T+bg) * ((softmax_banded(QK^T*s)V)@Wo^T+bo))
// Round 4: HMMA GEMM rebuilt (64x64 warp tiles, 3-stage cp.async, 2 CTA/SM);
//          attention PV via ldmatrix.trans (no smem transpose), async V load.
// (tcgen05 unavailable: harness compiles via virtual arch compute_100.)
// ---------------------------------------------------------------------------

#define BATCH 16
#define SEQ   512
#define DIM   1024
#define HEADS 16
#define HDIM  64
#define ROWS  (BATCH*SEQ)          // 8192
#define NELEM (ROWS*DIM)           // 8388608

// ---------------- scratch ---------------------------------------------------
static __device__ __align__(16) __nv_bfloat16 g_hb[NELEM];
static __device__ __align__(16) __nv_bfloat16 g_cb[NELEM];
static __device__ __align__(16) __nv_bfloat16 g_w5[5*DIM*DIM];   // Wq,Wk,Wv,Wo,Wg
static __device__ __align__(16) __nv_bfloat16 g_qs[NELEM];
static __device__ __align__(16) __nv_bfloat16 g_ks[NELEM];
static __device__ __align__(16) __nv_bfloat16 g_vs[NELEM];
static __device__ __align__(16) __nv_bfloat16 g_gs[NELEM];
static __device__ __align__(16) __nv_bfloat16 g_at[NELEM];
static __device__ __align__(16) float         g_z [NELEM];

// ---------------- PTX helpers -----------------------------------------------
__device__ __forceinline__ uint32_t smem_u32(const void* p) {
    return (uint32_t)__cvta_generic_to_shared(p);
}
__device__ __forceinline__ void cp_async16(uint32_t dst, const void* src) {
    asm volatile("cp.async.cg.shared.global [%0], [%1], 16;\n" :: "r"(dst), "l"(src));
}
__device__ __forceinline__ void cp_commit() { asm volatile("cp.async.commit_group;\n"); }
template <int N>
__device__ __forceinline__ void cp_wait_n() { asm volatile("cp.async.wait_group %0;\n" :: "n"(N)); }
__device__ __forceinline__ void cp_wait0()  { asm volatile("cp.async.wait_group 0;\n"); }

__device__ __forceinline__ void ldm_x4(uint32_t& r0, uint32_t& r1, uint32_t& r2, uint32_t& r3,
                                       uint32_t addr) {
    asm volatile("ldmatrix.sync.aligned.m8n8.x4.shared.b16 {%0,%1,%2,%3},[%4];\n"
                 : "=r"(r0), "=r"(r1), "=r"(r2), "=r"(r3) : "r"(addr));
}
__device__ __forceinline__ void ldm_x4_t(uint32_t& r0, uint32_t& r1, uint32_t& r2, uint32_t& r3,
                                         uint32_t addr) {
    asm volatile("ldmatrix.sync.aligned.m8n8.x4.trans.shared.b16 {%0,%1,%2,%3},[%4];\n"
                 : "=r"(r0), "=r"(r1), "=r"(r2), "=r"(r3) : "r"(addr));
}
__device__ __forceinline__ void mma16816(float* c, const uint32_t* a, const uint32_t* b) {
    asm volatile(
        "mma.sync.aligned.m16n8k16.row.col.f32.bf16.bf16.f32 "
        "{%0,%1,%2,%3},{%4,%5,%6,%7},{%8,%9},{%0,%1,%2,%3};\n"
        : "+f"(c[0]), "+f"(c[1]), "+f"(c[2]), "+f"(c[3])
        : "r"(a[0]), "r"(a[1]), "r"(a[2]), "r"(a[3]), "r"(b[0]), "r"(b[1]));
}
__device__ __forceinline__ uint32_t packbf(float a, float b) {
    __nv_bfloat162 h = __floats2bfloat162_rn(a, b);
    return *reinterpret_cast<const uint32_t*>(&h);
}

// ---------------- fp32 -> bf16 converts -------------------------------------
__global__ __launch_bounds__(256, 4) void cvt_act_kernel(
    const float4* __restrict__ h, const float4* __restrict__ c)
{
    const int n4 = NELEM / 4;
    __nv_bfloat162* yh = (__nv_bfloat162*)g_hb;
    __nv_bfloat162* yc = (__nv_bfloat162*)g_cb;
    for (int i = blockIdx.x * blockDim.x + threadIdx.x; i < n4;
         i += gridDim.x * blockDim.x) {
        float4 v = h[i];
        yh[2*i]   = __floats2bfloat162_rn(v.x, v.y);
        yh[2*i+1] = __floats2bfloat162_rn(v.z, v.w);
        float4 u = c[i];
        yc[2*i]   = __floats2bfloat162_rn(u.x, u.y);
        yc[2*i+1] = __floats2bfloat162_rn(u.z, u.w);
    }
}
__global__ __launch_bounds__(256, 4) void cvt_w_kernel(
    const float4* __restrict__ w0, const float4* __restrict__ w1,
    const float4* __restrict__ w2, const float4* __restrict__ w3,
    const float4* __restrict__ w4)
{
    const float4* src[5] = {w0, w1, w2, w3, w4};
    const int n4 = (DIM * DIM) / 4;
    const float4* x = src[blockIdx.y];
    __nv_bfloat162* y = (__nv_bfloat162*)(g_w5 + (size_t)blockIdx.y * DIM * DIM);
    for (int i = blockIdx.x * blockDim.x + threadIdx.x; i < n4;
         i += gridDim.x * blockDim.x) {
        float4 v = x[i];
        y[2*i]   = __floats2bfloat162_rn(v.x, v.y);
        y[2*i+1] = __floats2bfloat162_rn(v.z, v.w);
    }
}

// ---------------- HMMA GEMM --------------------------------------------------
// C[M,N] = A[M,K] @ W[N,K]^T (+bias, epilogue).
// CTA 128x128, 128 threads = 4 warps (2m x 2n), warp tile 64x64.
// K chunks of 32, 3-stage cp.async pipeline. 2 CTAs/SM target.
// MODE 0: fused 4-GEMM launch (blockIdx.z selects A/W/bias/out), bf16 out.
// MODE 1: fp32 out = 0.5*h + 0.5*sigmoid(gate)*(acc+bias).

struct GemmArgs {
    const __nv_bfloat16* A[4];
    const __nv_bfloat16* W[4];
    const float*         bias[4];
    __nv_bfloat16*       out[4];
};

#define NKT       32                 // 1024/32
#define STG_B     20480              // per stage: A 10240 + B 10240 (stride 40 hw)
#define HG_SMEM   (3*STG_B)          // 61440

template <int MODE>
__global__ __launch_bounds__(128, 2)
void hgemm_kernel(GemmArgs ga,
                  const __nv_bfloat16* __restrict__ gate,
                  const float* __restrict__ hres,
                  float* __restrict__ outf)
{
    extern __shared__ char dsm[];
    const uint32_t stg0 = smem_u32(dsm);

    const int tid  = threadIdx.x;
    const int lane = tid & 31;
    const int warp = tid >> 5;
    const int wm   = warp & 1;        // 2 warps in m
    const int wn   = warp >> 1;       // 2 warps in n
    const int z    = (MODE == 0) ? blockIdx.z : 0;
    const int m0   = blockIdx.y * 128;
    const int n0   = blockIdx.x * 128;

    const __nv_bfloat16* A = ga.A[z];
    const __nv_bfloat16* W = ga.W[z];
    const float*      bias = ga.bias[z];

    float acc[4][8][4];
#pragma unroll
    for (int i = 0; i < 4; i++)
#pragma unroll
        for (int j = 0; j < 8; j++)
#pragma unroll
            for (int e = 0; e < 4; e++) acc[i][j][e] = 0.f;

    auto load_stage = [&](int kt, int buf) {
        const uint32_t sa = stg0 + buf * STG_B;
        const uint32_t sb = sa + 10240;
        const int k0 = kt * 32;
#pragma unroll
        for (int i = 0; i < 4; i++) {
            int idx = i * 128 + tid;          // 0..511
            int r   = idx >> 2;               // 0..127
            int cg  = (idx & 3) * 8;          // 0,8,16,24
            cp_async16(sa + r*80 + cg*2, A + (size_t)(m0 + r) * DIM + k0 + cg);
            cp_async16(sb + r*80 + cg*2, W + (size_t)(n0 + r) * DIM + k0 + cg);
        }
        cp_commit();
    };

    load_stage(0, 0);
    load_stage(1, 1);

    int buf = 0;
    for (int kt = 0; kt < NKT; kt++) {
        if (kt < NKT - 1) cp_wait_n<1>(); else cp_wait0();
        __syncthreads();
        if (kt + 2 < NKT) {
            int nb = buf + 2; if (nb >= 3) nb -= 3;
            load_stage(kt + 2, nb);
        }
        const uint32_t ca = stg0 + buf * STG_B;
        const uint32_t cb = ca + 10240;
#pragma unroll
        for (int ks = 0; ks < 2; ks++) {
            const int kk = ks * 16;
            uint32_t a[4][4];
#pragma unroll
            for (int i = 0; i < 4; i++) {
                int row = wm*64 + i*16 + (lane & 15);
                int col = kk + ((lane >> 4) << 3);
                ldm_x4(a[i][0], a[i][1], a[i][2], a[i][3], ca + row*80 + col*2);
            }
#pragma unroll
            for (int jp = 0; jp < 4; jp++) {
                uint32_t b[4];
                int nrow = wn*64 + jp*16 + (lane & 7) + ((lane >> 4) << 3);
                int col  = kk + (lane & 8);
                ldm_x4(b[0], b[1], b[2], b[3], cb + nrow*80 + col*2);
#pragma unroll
                for (int i = 0; i < 4; i++) {
                    mma16816(acc[i][2*jp],   a[i], b);
                    mma16816(acc[i][2*jp+1], a[i], b + 2);
                }
            }
        }
        __syncthreads();
        buf++; if (buf == 3) buf = 0;
    }

    // epilogue
#pragma unroll
    for (int i = 0; i < 4; i++) {
        int r0 = m0 + wm*64 + i*16 + (lane >> 2);
#pragma unroll
        for (int j = 0; j < 8; j++) {
            int c = n0 + wn*64 + j*8 + 2*(lane & 3);
            float b0 = bias[c], b1 = bias[c+1];
            float v00 = acc[i][j][0] + b0, v01 = acc[i][j][1] + b1;
            float v10 = acc[i][j][2] + b0, v11 = acc[i][j][3] + b1;
            size_t i0 = (size_t)r0 * DIM + c;
            size_t i1 = (size_t)(r0 + 8) * DIM + c;
            if (MODE == 0) {
                *(uint32_t*)(ga.out[z] + i0) = packbf(v00, v01);
                *(uint32_t*)(ga.out[z] + i1) = packbf(v10, v11);
            } else {
                __nv_bfloat162 ga0 = *(const __nv_bfloat162*)(gate + i0);
                float2 h0 = *(const float2*)(hres + i0);
                float2 o0;
                o0.x = 0.5f*h0.x + 0.5f * (1.f/(1.f+__expf(-__bfloat162float(ga0.x)))) * v00;
                o0.y = 0.5f*h0.y + 0.5f * (1.f/(1.f+__expf(-__bfloat162float(ga0.y)))) * v01;
                *(float2*)(outf + i0) = o0;
                __nv_bfloat162 ga1 = *(const __nv_bfloat162*)(gate + i1);
                float2 h1 = *(const float2*)(hres + i1);
                float2 o1;
                o1.x = 0.5f*h1.x + 0.5f * (1.f/(1.f+__expf(-__bfloat162float(ga1.x)))) * v10;
                o1.y = 0.5f*h1.y + 0.5f * (1.f/(1.f+__expf(-__bfloat162float(ga1.y)))) * v11;
                *(float2*)(outf + i1) = o1;
            }
        }
    }
}

// ---------------- banded attention ------------------------------------------
// CTA = (qtile t, head h, batch b); 64 queries, up to 192 keys [q0-64, q0+127].
// 4 warps; warp w owns q rows [w*16, w*16+16).
// Q/K/V all loaded via cp.async; V wait deferred past softmax.
// PV uses ldmatrix.trans directly on row-major V tile (no smem transpose).

#define ATT_SMEM ((64 + 192 + 192) * 72 * 2)   // 64512 bytes

__global__ __launch_bounds__(128, 2) void attn_kernel(
    const __nv_bfloat16* __restrict__ Q, const __nv_bfloat16* __restrict__ Kp,
    const __nv_bfloat16* __restrict__ V, __nv_bfloat16* __restrict__ O)
{
    extern __shared__ char asm_[];
    const uint32_t Qs = smem_u32(asm_);          // [64][72] bf16
    const uint32_t Ks = Qs + 64*72*2;            // [192][72]
    const uint32_t Vs = Ks + 192*72*2;           // [192][72]

    const int t = blockIdx.x, h = blockIdx.y, b = blockIdx.z;
    const int tid = threadIdx.x, lane = tid & 31, w = tid >> 5;
    const int q0 = t * 64;
    int lo = q0 - 64; if (lo < 0) lo = 0;
    int hi = q0 + 127; if (hi > SEQ - 1) hi = SEQ - 1;
    const int nk = hi - lo + 1;
    const size_t base = ((size_t)b * SEQ) * DIM + h * HDIM;

    // group 0: Q + K
    for (int c = tid; c < 512; c += 128) {
        int r = c >> 3, off = (c & 7) << 3;
        cp_async16(Qs + (r*72 + off)*2, Q + base + (size_t)(q0 + r) * DIM + off);
    }
    for (int c = tid; c < 1536; c += 128) {
        int jj = c >> 3, off = (c & 7) << 3;
        if (jj < nk)
            cp_async16(Ks + (jj*72 + off)*2, Kp + base + (size_t)(lo + jj) * DIM + off);
        // stale smem in tail rows is fine: masked to -inf before softmax
    }
    cp_commit();
    // group 1: V (tail rows must be ZERO: P=0 * NaN would poison)
    for (int c = tid; c < 1536; c += 128) {
        int jj = c >> 3, off = (c & 7) << 3;
        if (jj < nk)
            cp_async16(Vs + (jj*72 + off)*2, V + base + (size_t)(lo + jj) * DIM + off);
        else
            *(uint4*)(asm_ + (Vs - Qs) + (jj*72 + off)*2) = make_uint4(0u,0u,0u,0u);
    }
    cp_commit();

    cp_wait_n<1>();     // Q + K ready
    __syncthreads();

    // S = Q K^T  (16 x 192 per warp)
    float s[24][4];
#pragma unroll
    for (int j = 0; j < 24; j++)
#pragma unroll
        for (int e = 0; e < 4; e++) s[j][e] = 0.f;

#pragma unroll
    for (int ks = 0; ks < 4; ks++) {
        int kk = ks * 16;
        uint32_t a[4];
        {
            int row = w*16 + (lane & 15);
            int col = kk + ((lane >> 4) << 3);
            ldm_x4(a[0], a[1], a[2], a[3], Qs + (row*72 + col)*2);
        }
#pragma unroll
        for (int jp = 0; jp < 12; jp++) {
            uint32_t bb[4];
            int nrow = jp*16 + (lane & 7) + ((lane >> 4) << 3);
            int col  = kk + (lane & 8);
            ldm_x4(bb[0], bb[1], bb[2], bb[3], Ks + (nrow*72 + col)*2);
            mma16816(s[2*jp],   a, bb);
            mma16816(s[2*jp+1], a, bb + 2);
        }
    }

    // mask + scale + softmax (register-resident)
    const int r0 = q0 + w*16 + (lane >> 2);
    const int r1 = r0 + 8;
    float m0 = -1e30f, m1 = -1e30f;
#pragma unroll
    for (int j = 0; j < 24; j++) {
        int kg = lo + j*8 + 2*(lane & 3);
        int d00 = r0 - kg, d01 = r0 - kg - 1, d10 = r1 - kg, d11 = r1 - kg - 1;
        bool v0 = (kg     <= hi) && (d00 <= 64) && (d00 >= -64);
        bool v1 = (kg + 1 <= hi) && (d01 <= 64) && (d01 >= -64);
        bool v2 = (kg     <= hi) && (d10 <= 64) && (d10 >= -64);
        bool v3 = (kg + 1 <= hi) && (d11 <= 64) && (d11 >= -64);
        s[j][0] = v0 ? s[j][0] * 0.125f : -1e30f;
        s[j][1] = v1 ? s[j][1] * 0.125f : -1e30f;
        s[j][2] = v2 ? s[j][2] * 0.125f : -1e30f;
        s[j][3] = v3 ? s[j][3] * 0.125f : -1e30f;
        m0 = fmaxf(m0, fmaxf(s[j][0], s[j][1]));
        m1 = fmaxf(m1, fmaxf(s[j][2], s[j][3]));
    }
    m0 = fmaxf(m0, __shfl_xor_sync(0xffffffffu, m0, 1));
    m0 = fmaxf(m0, __shfl_xor_sync(0xffffffffu, m0, 2));
    m1 = fmaxf(m1, __shfl_xor_sync(0xffffffffu, m1, 1));
    m1 = fmaxf(m1, __shfl_xor_sync(0xffffffffu, m1, 2));

    float sum0 = 0.f, sum1 = 0.f;
#pragma unroll
    for (int j = 0; j < 24; j++) {
        s[j][0] = __expf(s[j][0] - m0); sum0 += s[j][0];
        s[j][1] = __expf(s[j][1] - m0); sum0 += s[j][1];
        s[j][2] = __expf(s[j][2] - m1); sum1 += s[j][2];
        s[j][3] = __expf(s[j][3] - m1); sum1 += s[j][3];
    }
    sum0 += __shfl_xor_sync(0xffffffffu, sum0, 1);
    sum0 += __shfl_xor_sync(0xffffffffu, sum0, 2);
    sum1 += __shfl_xor_sync(0xffffffffu, sum1, 1);
    sum1 += __shfl_xor_sync(0xffffffffu, sum1, 2);

    cp_wait0();          // V ready
    __syncthreads();

    // O = P V  (16 x 64 per warp) — B frags via ldmatrix.trans on [k][d] tile
    float o_[8][4];
#pragma unroll
    for (int j = 0; j < 8; j++)
#pragma unroll
        for (int e = 0; e < 4; e++) o_[j][e] = 0.f;

#pragma unroll
    for (int kk = 0; kk < 12; kk++) {
        uint32_t pa[4];
        pa[0] = packbf(s[2*kk][0],   s[2*kk][1]);
        pa[1] = packbf(s[2*kk][2],   s[2*kk][3]);
        pa[2] = packbf(s[2*kk+1][0], s[2*kk+1][1]);
        pa[3] = packbf(s[2*kk+1][2], s[2*kk+1][3]);
#pragma unroll
        for (int dp = 0; dp < 4; dp++) {
            uint32_t bb[4];
            int krow = kk*16 + (lane & 15);
            int dcol = dp*16 + ((lane >> 4) << 3);
            ldm_x4_t(bb[0], bb[1], bb[2], bb[3], Vs + (krow*72 + dcol)*2);
            mma16816(o_[2*dp],   pa, bb);
            mma16816(o_[2*dp+1], pa, bb + 2);
        }
    }

    const float inv0 = 1.f / sum0, inv1 = 1.f / sum1;
#pragma unroll
    for (int dj = 0; dj < 8; dj++) {
        int cc = dj*8 + 2*(lane & 3);
        *(uint32_t*)(O + base + (size_t)r0 * DIM + cc) = packbf(o_[dj][0]*inv0, o_[dj][1]*inv0);
        *(uint32_t*)(O + base + (size_t)r1 * DIM + cc) = packbf(o_[dj][2]*inv1, o_[dj][3]*inv1);
    }
}

// ---------------- LayerNorm --------------------------------------------------
__global__ __launch_bounds__(256, 1) void ln_kernel(
    const float* __restrict__ z, const float* __restrict__ gamma,
    const float* __restrict__ beta, float* __restrict__ out)
{
    __shared__ float rs[8], rq[8];
    __shared__ float s_mean, s_rstd;
    const int row = blockIdx.x, tid = threadIdx.x;
    const float4 x = ((const float4*)(z + (size_t)row * DIM))[tid];
    float s = x.x + x.y + x.z + x.w;
    float q = x.x*x.x + x.y*x.y + x.z*x.z + x.w*x.w;
#pragma unroll
    for (int o = 16; o > 0; o >>= 1) {
        s += __shfl_xor_sync(0xffffffffu, s, o);
        q += __shfl_xor_sync(0xffffffffu, q, o);
    }
    if ((tid & 31) == 0) { rs[tid >> 5] = s; rq[tid >> 5] = q; }
    __syncthreads();
    if (tid == 0) {
        float S = 0.f, Q2 = 0.f;
#pragma unroll
        for (int i = 0; i < 8; i++) { S += rs[i]; Q2 += rq[i]; }
        float mean = S * (1.f / DIM);
        float var  = Q2 * (1.f / DIM) - mean * mean;
        s_mean = mean;
        s_rstd = rsqrtf(var + 1e-5f);
    }
    __syncthreads();
    const float mean = s_mean, rstd = s_rstd;
    const float4 gm = ((const float4*)gamma)[tid];
    const float4 bt = ((const float4*)beta)[tid];
    float4 y;
    y.x = (x.x - mean) * rstd * gm.x + bt.x;
    y.y = (x.y - mean) * rstd * gm.y + bt.y;
    y.z = (x.z - mean) * rstd * gm.z + bt.z;
    y.w = (x.w - mean) * rstd * gm.w + bt.w;
    ((float4*)(out + (size_t)row * DIM))[tid] = y;
}

// ---------------- launch -----------------------------------------------------
extern "C" void kernel_launch(void* const* d_in, const int* in_sizes, int n_in,
                              void* d_out, int out_size)
{
    const float* hidden = (const float*)d_in[0];
    const float* cross  = (const float*)d_in[1];
    const float* Wq = (const float*)d_in[2];  const float* bq = (const float*)d_in[3];
    const float* Wk = (const float*)d_in[4];  const float* bk = (const float*)d_in[5];
    const float* Wv = (const float*)d_in[6];  const float* bv = (const float*)d_in[7];
    const float* Wo = (const float*)d_in[8];  const float* bo = (const float*)d_in[9];
    const float* Wg = (const float*)d_in[10]; const float* bg = (const float*)d_in[11];
    const float* gamma = (const float*)d_in[12];
    const float* beta  = (const float*)d_in[13];
    float* out = (float*)d_out;

    void *hb, *cb, *w5, *qs, *ks, *vs, *gs, *at, *zz;
    cudaGetSymbolAddress(&hb, g_hb); cudaGetSymbolAddress(&cb, g_cb);
    cudaGetSymbolAddress(&w5, g_w5);
    cudaGetSymbolAddress(&qs, g_qs); cudaGetSymbolAddress(&ks, g_ks);
    cudaGetSymbolAddress(&vs, g_vs); cudaGetSymbolAddress(&gs, g_gs);
    cudaGetSymbolAddress(&at, g_at); cudaGetSymbolAddress(&zz, g_z);

    const __nv_bfloat16* wq = (const __nv_bfloat16*)w5;
    const __nv_bfloat16* wk = wq + (size_t)DIM * DIM;
    const __nv_bfloat16* wv = wk + (size_t)DIM * DIM;
    const __nv_bfloat16* wo = wv + (size_t)DIM * DIM;
    const __nv_bfloat16* wg = wo + (size_t)DIM * DIM;

    cudaFuncSetAttribute(hgemm_kernel<0>, cudaFuncAttributeMaxDynamicSharedMemorySize, HG_SMEM);
    cudaFuncSetAttribute(hgemm_kernel<1>, cudaFuncAttributeMaxDynamicSharedMemorySize, HG_SMEM);
    cudaFuncSetAttribute(attn_kernel,     cudaFuncAttributeMaxDynamicSharedMemorySize, ATT_SMEM);

    cvt_act_kernel<<<2048, 256>>>((const float4*)hidden, (const float4*)cross);
    cvt_w_kernel<<<dim3(128, 5), 256>>>((const float4*)Wq, (const float4*)Wk,
                                        (const float4*)Wv, (const float4*)Wo,
                                        (const float4*)Wg);

    // fused Q,K,V,Gate projections (blockIdx.z selects)
    GemmArgs ga;
    ga.A[0] = (const __nv_bfloat16*)hb; ga.W[0] = wq; ga.bias[0] = bq; ga.out[0] = (__nv_bfloat16*)qs;
    ga.A[1] = (const __nv_bfloat16*)cb; ga.W[1] = wk; ga.bias[1] = bk; ga.out[1] = (__nv_bfloat16*)ks;
    ga.A[2] = (const __nv_bfloat16*)cb; ga.W[2] = wv; ga.bias[2] = bv; ga.out[2] = (__nv_bfloat16*)vs;
    ga.A[3] = (const __nv_bfloat16*)hb; ga.W[3] = wg; ga.bias[3] = bg; ga.out[3] = (__nv_bfloat16*)gs;
    hgemm_kernel<0><<<dim3(DIM/128, ROWS/128, 4), 128, HG_SMEM>>>(ga, nullptr, nullptr, nullptr);

    attn_kernel<<<dim3(SEQ / 64, HEADS, BATCH), 128, ATT_SMEM>>>(
        (const __nv_bfloat16*)qs, (const __nv_bfloat16*)ks,
        (const __nv_bfloat16*)vs, (__nv_bfloat16*)at);

    // output projection + gate + residual blend
    GemmArgs go;
    go.A[0] = (const __nv_bfloat16*)at; go.W[0] = wo; go.bias[0] = bo; go.out[0] = nullptr;
    go.A[1] = go.A[0]; go.W[1] = go.W[0]; go.bias[1] = go.bias[0]; go.out[1] = nullptr;
    go.A[2] = go.A[0]; go.W[2] = go.W[0]; go.bias[2] = go.bias[0]; go.out[2] = nullptr;
    go.A[3] = go.A[0]; go.W[3] = go.W[0]; go.bias[3] = go.bias[0]; go.out[3] = nullptr;
    hgemm_kernel<1><<<dim3(DIM/128, ROWS/128, 1), 128, HG_SMEM>>>(
        go, (const __nv_bfloat16*)gs, hidden, (float*)zz);

    ln_kernel<<<ROWS, 256>>>((const float*)zz, gamma, beta, out);
    (void)in_sizes; (void)n_in; (void)out_size;
}